// round 4
// baseline (speedup 1.0000x reference)
#include <cuda_runtime.h>
#include <cuda_fp16.h>
#include <math.h>

#define N_NODES 100000
#define N_EDGES 1000000
#define KD 128
#define VD 64
#define AGGD 192   // KD + VD
#define NBLK 391   // ceil(N_NODES / 256)

// ---------------- scratch (static device allocations, graph-safe) ----------
__device__ __align__(16) int4   g_packed[N_EDGES];   // {h, a, v, bitcast(score)}
__device__ __align__(16) int4   g_csr[N_EDGES];      // CSR-ordered copies
__device__ __align__(16) __half g_attH[N_NODES * KD];
__device__ __align__(16) __half g_valH[N_NODES * VD];
__device__ float g_rowsum[N_NODES];
__device__ float g_sent[N_NODES];
__device__ float g_satt[N_NODES];
__device__ int   g_deg[N_NODES];
__device__ int   g_off[N_NODES];
__device__ int   g_cursor[N_NODES];
__device__ int   g_bsum[NBLK];
__device__ int   g_boff[NBLK];
__device__ int   g_idx64;

// ---------------- dtype sniff: int64 vs int32 triples ----------------------
__global__ void sniff_kernel(const int* tri32) {
    if (threadIdx.x == 0 && blockIdx.x == 0) {
        int is64 = 1;
        #pragma unroll 1
        for (int i = 0; i < 256; i++) {
            if (tri32[2 * i + 1] != 0) { is64 = 0; break; }
        }
        g_idx64 = is64;
    }
}

// ------- per-node score pre-reduction + att fp16 conversion + resets --------
__global__ void score_pre_kernel(const float* __restrict__ ent,
                                 const float* __restrict__ att,
                                 const float* __restrict__ aw) {
    int warp = (blockIdx.x * blockDim.x + threadIdx.x) >> 5;
    int lane = threadIdx.x & 31;
    if (warp >= N_NODES) return;

    const float4* ent4 = reinterpret_cast<const float4*>(ent);
    const float4* att4 = reinterpret_cast<const float4*>(att);
    const float4* aw4  = reinterpret_cast<const float4*>(aw);

    float4 e = ent4[warp * 32 + lane];
    float4 a = att4[warp * 32 + lane];
    float4 we = __ldg(&aw4[lane]);
    float4 wa = __ldg(&aw4[32 + lane]);

    // convert att row to fp16 (4 halves per lane -> 8B store)
    __half2 h0 = __floats2half2_rn(a.x, a.y);
    __half2 h1 = __floats2half2_rn(a.z, a.w);
    uint2 packed;
    packed.x = *reinterpret_cast<unsigned*>(&h0);
    packed.y = *reinterpret_cast<unsigned*>(&h1);
    *reinterpret_cast<uint2*>(g_attH + warp * KD + lane * 4) = packed;

    float se = e.x * we.x + e.y * we.y + e.z * we.z + e.w * we.w;
    float sa = a.x * wa.x + a.y * wa.y + a.z * wa.z + a.w * wa.w;
    #pragma unroll
    for (int o = 16; o; o >>= 1) {
        se += __shfl_xor_sync(0xFFFFFFFFu, se, o);
        sa += __shfl_xor_sync(0xFFFFFFFFu, sa, o);
    }
    if (lane == 0) {
        g_sent[warp] = se;
        g_satt[warp] = sa;
        g_rowsum[warp] = 0.f;
        g_deg[warp] = 0;
    }
}

// ---------------- val fp16 conversion ---------------------------------------
__global__ void valconv_kernel(const float* __restrict__ valf) {
    int i = blockIdx.x * blockDim.x + threadIdx.x;          // float4 index
    int n4 = N_NODES * VD / 4;
    if (i >= n4) return;
    float4 v = reinterpret_cast<const float4*>(valf)[i];
    __half2 h0 = __floats2half2_rn(v.x, v.y);
    __half2 h1 = __floats2half2_rn(v.z, v.w);
    uint2 packed;
    packed.x = *reinterpret_cast<unsigned*>(&h0);
    packed.y = *reinterpret_cast<unsigned*>(&h1);
    *reinterpret_cast<uint2*>(g_valH + i * 4) = packed;
}

// ---------------- pass A: per-edge score + degree histogram -----------------
__global__ void score_edge_kernel(const void* __restrict__ tri,
                                  const float* __restrict__ ab) {
    int e = blockIdx.x * blockDim.x + threadIdx.x;
    if (e >= N_EDGES) return;
    int h, a, v;
    if (g_idx64) {
        const long long* t = reinterpret_cast<const long long*>(tri) + 3LL * e;
        h = (int)t[0]; a = (int)t[1]; v = (int)t[2];
    } else {
        const int* t = reinterpret_cast<const int*>(tri) + 3 * e;
        h = t[0]; a = t[1]; v = t[2];
    }
    float s = g_sent[h] + g_satt[a] + __ldg(&ab[0]);
    s = s > 0.f ? s : 0.2f * s;                 // leaky_relu(0.2)
    float sc = __expf(s);
    atomicAdd(&g_rowsum[h], sc);
    atomicAdd(&g_deg[h], 1);
    g_packed[e] = make_int4(h, a, v, __float_as_int(sc));
}

// ---------------- 3-phase exclusive scan over degrees -----------------------
__global__ void scan_a_kernel() {
    __shared__ int sh[256];
    int t = threadIdx.x, b = blockIdx.x;
    int node = b * 256 + t;
    sh[t] = (node < N_NODES) ? g_deg[node] : 0;
    __syncthreads();
    #pragma unroll
    for (int d = 128; d; d >>= 1) {
        if (t < d) sh[t] += sh[t + d];
        __syncthreads();
    }
    if (t == 0) g_bsum[b] = sh[0];
}

__global__ void scan_b_kernel() {
    __shared__ int sh[512];
    int t = threadIdx.x;
    int v = (t < NBLK) ? g_bsum[t] : 0;
    sh[t] = v;
    __syncthreads();
    #pragma unroll
    for (int d = 1; d < 512; d <<= 1) {
        int x = (t >= d) ? sh[t - d] : 0;
        __syncthreads();
        sh[t] += x;
        __syncthreads();
    }
    if (t < NBLK) g_boff[t] = sh[t] - v;   // exclusive
}

__global__ void scan_c_kernel() {
    __shared__ int sh[256];
    int t = threadIdx.x, b = blockIdx.x;
    int node = b * 256 + t;
    int v = (node < N_NODES) ? g_deg[node] : 0;
    sh[t] = v;
    __syncthreads();
    #pragma unroll
    for (int d = 1; d < 256; d <<= 1) {
        int x = (t >= d) ? sh[t - d] : 0;
        __syncthreads();
        sh[t] += x;
        __syncthreads();
    }
    if (node < N_NODES) {
        int off = g_boff[b] + sh[t] - v;
        g_off[node] = off;
        g_cursor[node] = off;
    }
}

// ---------------- pass B: permute records into CSR order --------------------
__global__ void fill_kernel() {
    int e = blockIdx.x * blockDim.x + threadIdx.x;
    if (e >= N_EDGES) return;
    int4 p = g_packed[e];
    int pos = atomicAdd(&g_cursor[p.x], 1);
    g_csr[pos] = p;
}

// ======== fused gather-aggregate + node GEMM (warp-specialized) =============
#define FUSE_THREADS 512
#define PROD_WARPS 8
#define NPW 8                         // nodes per warp (both roles)
#define TILE_NODES 64                 // PROD_WARPS * NPW
#define NTILES ((N_NODES + TILE_NODES - 1) / TILE_NODES)   // 1563
#define BUF_FLOATS (TILE_NODES * AGGD)                     // 12288

__device__ __forceinline__ unsigned long long pack2(float x, float y) {
    unsigned long long r;
    asm("mov.b64 %0, {%1, %2};" : "=l"(r) : "f"(x), "f"(y));
    return r;
}
__device__ __forceinline__ void unpack2(unsigned long long p, float& x, float& y) {
    asm("mov.b64 {%0, %1}, %2;" : "=f"(x), "=f"(y) : "l"(p));
}
__device__ __forceinline__ void ffma2(unsigned long long& d,
                                      unsigned long long a,
                                      unsigned long long b) {
    asm("fma.rn.f32x2 %0, %1, %2, %0;" : "+l"(d) : "l"(a), "l"(b));
}

__device__ __forceinline__ void gather_edge(int a, int v, float s, int lane,
                                            float4& accA, float4& accV) {
    uint2 ua = *reinterpret_cast<const uint2*>(g_attH + a * KD + lane * 4);
    __half2 h0 = *reinterpret_cast<__half2*>(&ua.x);
    __half2 h1 = *reinterpret_cast<__half2*>(&ua.y);
    float2 f0 = __half22float2(h0);
    float2 f1 = __half22float2(h1);
    accA.x += f0.x * s; accA.y += f0.y * s;
    accA.z += f1.x * s; accA.w += f1.y * s;
    if (lane < 16) {
        uint2 uv = *reinterpret_cast<const uint2*>(g_valH + v * VD + lane * 4);
        __half2 g0 = *reinterpret_cast<__half2*>(&uv.x);
        __half2 g1 = *reinterpret_cast<__half2*>(&uv.y);
        float2 e0 = __half22float2(g0);
        float2 e1 = __half22float2(g1);
        accV.x += e0.x * s; accV.y += e0.y * s;
        accV.z += e1.x * s; accV.w += e1.y * s;
    }
}

__global__ void __launch_bounds__(FUSE_THREADS, 1)
fused_kernel(const float* __restrict__ ent,
             const float* __restrict__ W,
             float* __restrict__ out) {
    extern __shared__ float sh[];
    float* Wsh = sh;                       // 24576 floats (98304 B)
    float* buf = sh + AGGD * KD;           // 2 * 12288 floats (98304 B)

    int tid  = threadIdx.x;
    int wid  = tid >> 5;
    int lane = tid & 31;

    for (int i = tid; i < AGGD * KD / 4; i += FUSE_THREADS)
        reinterpret_cast<float4*>(Wsh)[i] = reinterpret_cast<const float4*>(W)[i];
    __syncthreads();

    int ntiles = (NTILES - blockIdx.x + gridDim.x - 1) / gridDim.x;

    for (int k = 0; k <= ntiles; k++) {
        if (wid < PROD_WARPS && k < ntiles) {
            // ---------------- producer: gather-aggregate 8 nodes ------------
            int tile = blockIdx.x + k * gridDim.x;
            float* bufk = buf + (k & 1) * BUF_FLOATS;
            int nbase = tile * TILE_NODES + wid * NPW;
            #pragma unroll 1
            for (int n = 0; n < NPW; n++) {
                int node = nbase + n;
                float4 accA = make_float4(0.f, 0.f, 0.f, 0.f);
                float4 accV = make_float4(0.f, 0.f, 0.f, 0.f);
                if (node < N_NODES) {
                    int beg = g_off[node];
                    int deg = g_deg[node];
                    for (int base = 0; base < deg; base += 32) {
                        int4 r = make_int4(0, 0, 0, 0);
                        if (base + lane < deg) r = g_csr[beg + base + lane];
                        int m = min(32, deg - base);
                        int i = 0;
                        for (; i + 4 <= m; i += 4) {
                            int   A[4], V[4];
                            float S[4];
                            #pragma unroll
                            for (int u = 0; u < 4; u++) {
                                A[u] = __shfl_sync(0xFFFFFFFFu, r.y, i + u);
                                V[u] = __shfl_sync(0xFFFFFFFFu, r.z, i + u);
                                S[u] = __int_as_float(
                                    __shfl_sync(0xFFFFFFFFu, r.w, i + u));
                            }
                            #pragma unroll
                            for (int u = 0; u < 4; u++)
                                gather_edge(A[u], V[u], S[u], lane, accA, accV);
                        }
                        for (; i < m; i++) {
                            int   a = __shfl_sync(0xFFFFFFFFu, r.y, i);
                            int   v = __shfl_sync(0xFFFFFFFFu, r.z, i);
                            float s = __int_as_float(
                                __shfl_sync(0xFFFFFFFFu, r.w, i));
                            gather_edge(a, v, s, lane, accA, accV);
                        }
                    }
                }
                float* row = bufk + (wid * NPW + n) * AGGD;
                *reinterpret_cast<float4*>(row + lane * 4) = accA;
                if (lane < 16)
                    *reinterpret_cast<float4*>(row + KD + lane * 4) = accV;
            }
        } else if (wid >= PROD_WARPS && k >= 1) {
            // ---------------- consumer: 192x128 matvec + epilogue -----------
            int tile = blockIdx.x + (k - 1) * gridDim.x;
            const float* bufk = buf + ((k - 1) & 1) * BUF_FLOATS;
            int cw = wid - PROD_WARPS;
            int nbase = tile * TILE_NODES + cw * NPW;

            unsigned long long acc01[NPW], acc23[NPW];
            #pragma unroll
            for (int n = 0; n < NPW; n++) { acc01[n] = 0ull; acc23[n] = 0ull; }

            #pragma unroll 1
            for (int j = 0; j < AGGD; j += 4) {
                float4 aj[NPW];
                #pragma unroll
                for (int n = 0; n < NPW; n++)
                    aj[n] = *reinterpret_cast<const float4*>(
                        bufk + (cw * NPW + n) * AGGD + j);
                #pragma unroll
                for (int jj = 0; jj < 4; jj++) {
                    float4 w = reinterpret_cast<const float4*>(Wsh)[(j + jj) * 32 + lane];
                    unsigned long long w01 = pack2(w.x, w.y);
                    unsigned long long w23 = pack2(w.z, w.w);
                    #pragma unroll
                    for (int n = 0; n < NPW; n++) {
                        float a = (jj == 0) ? aj[n].x : (jj == 1) ? aj[n].y
                                 : (jj == 2) ? aj[n].z : aj[n].w;
                        unsigned long long aa = pack2(a, a);
                        ffma2(acc01[n], aa, w01);
                        ffma2(acc23[n], aa, w23);
                    }
                }
            }

            #pragma unroll
            for (int n = 0; n < NPW; n++) {
                int node = nbase + n;
                if (node >= N_NODES) break;
                float c0, c1, c2, c3;
                unpack2(acc01[n], c0, c1);
                unpack2(acc23[n], c2, c3);

                float rs = g_rowsum[node];
                float inv = rs > 0.f ? 1.f / rs : 0.f;
                float4 e = reinterpret_cast<const float4*>(ent)[node * 32 + lane];

                float t0 = c0 * inv + e.x;
                float t1 = c1 * inv + e.y;
                float t2 = c2 * inv + e.z;
                float t3 = c3 * inv + e.w;
                float4 o;
                o.x = t0 > 0.f ? t0 : expm1f(t0);   // elu, alpha=1
                o.y = t1 > 0.f ? t1 : expm1f(t1);
                o.z = t2 > 0.f ? t2 : expm1f(t2);
                o.w = t3 > 0.f ? t3 : expm1f(t3);
                reinterpret_cast<float4*>(out)[node * 32 + lane] = o;
            }
        }
        __syncthreads();
    }
}

// ---------------- launch ----------------------------------------------------
extern "C" void kernel_launch(void* const* d_in, const int* in_sizes, int n_in,
                              void* d_out, int out_size) {
    const void*  triples = d_in[0];                       // [1e6, 3] int64/int32
    const float* ent     = (const float*)d_in[1];         // [1e5, 128]
    const float* attf    = (const float*)d_in[2];         // [1e5, 128]
    const float* valf    = (const float*)d_in[3];         // [1e5, 64]
    const float* aw      = (const float*)d_in[4];         // [256]
    const float* ab      = (const float*)d_in[5];         // [1]
    const float* W       = (const float*)d_in[6];         // [192, 128]
    float* out           = (float*)d_out;                 // [1e5, 128]

    static bool attr_set = false;
    size_t fuse_smem = (size_t)(AGGD * KD + 2 * BUF_FLOATS) * sizeof(float); // 196608
    if (!attr_set) {
        cudaFuncSetAttribute(fused_kernel, cudaFuncAttributeMaxDynamicSharedMemorySize,
                             (int)fuse_smem);
        attr_set = true;
    }

    sniff_kernel<<<1, 32>>>((const int*)triples);
    score_pre_kernel<<<(N_NODES + 7) / 8, 256>>>(ent, attf, aw);
    valconv_kernel<<<(N_NODES * VD / 4 + 255) / 256, 256>>>(valf);
    score_edge_kernel<<<(N_EDGES + 255) / 256, 256>>>(triples, ab);
    scan_a_kernel<<<NBLK, 256>>>();
    scan_b_kernel<<<1, 512>>>();
    scan_c_kernel<<<NBLK, 256>>>();
    fill_kernel<<<(N_EDGES + 255) / 256, 256>>>();
    fused_kernel<<<148, FUSE_THREADS, fuse_smem>>>(ent, W, out);
}

// round 5
// speedup vs baseline: 1.1274x; 1.1274x over previous
#include <cuda_runtime.h>
#include <cuda_fp16.h>
#include <math.h>

#define N_NODES 100000
#define N_EDGES 1000000
#define KD 128
#define VD 64
#define AGGD 192   // KD + VD
#define NBLK 391   // ceil(N_NODES / 256)

// ---------------- scratch (static device allocations, graph-safe) ----------
__device__ __align__(16) float  g_agg[N_NODES * AGGD];
__device__ __align__(16) int4   g_packed[N_EDGES];   // {h, a, v, bitcast(score)}
__device__ __align__(16) int4   g_csr[N_EDGES];      // CSR-ordered copies
__device__ __align__(16) __half g_attH[N_NODES * KD];
__device__ __align__(16) __half g_valH[N_NODES * VD];
__device__ float g_rowsum[N_NODES];
__device__ float g_sent[N_NODES];
__device__ float g_satt[N_NODES];
__device__ int   g_deg[N_NODES];
__device__ int   g_off[N_NODES];
__device__ int   g_cursor[N_NODES];
__device__ int   g_bsum[NBLK];
__device__ int   g_boff[NBLK];
__device__ int   g_idx64;

// ---------------- dtype sniff: int64 vs int32 triples (parallel) -----------
__global__ void sniff_kernel(const int* tri32) {
    int t = threadIdx.x;                       // 256 threads, coalesced loads
    int bad = (tri32[2 * t + 1] != 0) ? 1 : 0; // odd words zero iff int64
    int any = __syncthreads_or(bad);
    if (t == 0) g_idx64 = any ? 0 : 1;
}

// ------- per-node score pre-reduction + att fp16 conversion + resets --------
__global__ void score_pre_kernel(const float* __restrict__ ent,
                                 const float* __restrict__ att,
                                 const float* __restrict__ aw) {
    int warp = (blockIdx.x * blockDim.x + threadIdx.x) >> 5;
    int lane = threadIdx.x & 31;
    if (warp >= N_NODES) return;

    const float4* ent4 = reinterpret_cast<const float4*>(ent);
    const float4* att4 = reinterpret_cast<const float4*>(att);
    const float4* aw4  = reinterpret_cast<const float4*>(aw);

    float4 e = ent4[warp * 32 + lane];
    float4 a = att4[warp * 32 + lane];
    float4 we = __ldg(&aw4[lane]);
    float4 wa = __ldg(&aw4[32 + lane]);

    // convert att row to fp16 (4 halves per lane -> 8B store)
    __half2 h0 = __floats2half2_rn(a.x, a.y);
    __half2 h1 = __floats2half2_rn(a.z, a.w);
    uint2 packed;
    packed.x = *reinterpret_cast<unsigned*>(&h0);
    packed.y = *reinterpret_cast<unsigned*>(&h1);
    *reinterpret_cast<uint2*>(g_attH + warp * KD + lane * 4) = packed;

    float se = e.x * we.x + e.y * we.y + e.z * we.z + e.w * we.w;
    float sa = a.x * wa.x + a.y * wa.y + a.z * wa.z + a.w * wa.w;
    #pragma unroll
    for (int o = 16; o; o >>= 1) {
        se += __shfl_xor_sync(0xFFFFFFFFu, se, o);
        sa += __shfl_xor_sync(0xFFFFFFFFu, sa, o);
    }
    if (lane == 0) {
        g_sent[warp] = se;
        g_satt[warp] = sa;
        g_rowsum[warp] = 0.f;
        g_deg[warp] = 0;
    }
}

// ---------------- val fp16 conversion ---------------------------------------
__global__ void valconv_kernel(const float* __restrict__ valf) {
    int i = blockIdx.x * blockDim.x + threadIdx.x;          // float4 index
    int n4 = N_NODES * VD / 4;
    if (i >= n4) return;
    float4 v = reinterpret_cast<const float4*>(valf)[i];
    __half2 h0 = __floats2half2_rn(v.x, v.y);
    __half2 h1 = __floats2half2_rn(v.z, v.w);
    uint2 packed;
    packed.x = *reinterpret_cast<unsigned*>(&h0);
    packed.y = *reinterpret_cast<unsigned*>(&h1);
    *reinterpret_cast<uint2*>(g_valH + i * 4) = packed;
}

// ---------------- pass A: per-edge score + degree histogram -----------------
__global__ void score_edge_kernel(const void* __restrict__ tri,
                                  const float* __restrict__ ab) {
    int e = blockIdx.x * blockDim.x + threadIdx.x;
    if (e >= N_EDGES) return;
    int h, a, v;
    if (g_idx64) {
        const long long* t = reinterpret_cast<const long long*>(tri) + 3LL * e;
        h = (int)t[0]; a = (int)t[1]; v = (int)t[2];
    } else {
        const int* t = reinterpret_cast<const int*>(tri) + 3 * e;
        h = t[0]; a = t[1]; v = t[2];
    }
    float s = g_sent[h] + g_satt[a] + __ldg(&ab[0]);
    s = s > 0.f ? s : 0.2f * s;                 // leaky_relu(0.2)
    float sc = __expf(s);
    atomicAdd(&g_rowsum[h], sc);
    atomicAdd(&g_deg[h], 1);
    g_packed[e] = make_int4(h, a, v, __float_as_int(sc));
}

// ---------------- 3-phase exclusive scan over degrees -----------------------
__global__ void scan_a_kernel() {
    __shared__ int sh[256];
    int t = threadIdx.x, b = blockIdx.x;
    int node = b * 256 + t;
    sh[t] = (node < N_NODES) ? g_deg[node] : 0;
    __syncthreads();
    #pragma unroll
    for (int d = 128; d; d >>= 1) {
        if (t < d) sh[t] += sh[t + d];
        __syncthreads();
    }
    if (t == 0) g_bsum[b] = sh[0];
}

__global__ void scan_b_kernel() {
    __shared__ int sh[512];
    int t = threadIdx.x;
    int v = (t < NBLK) ? g_bsum[t] : 0;
    sh[t] = v;
    __syncthreads();
    #pragma unroll
    for (int d = 1; d < 512; d <<= 1) {
        int x = (t >= d) ? sh[t - d] : 0;
        __syncthreads();
        sh[t] += x;
        __syncthreads();
    }
    if (t < NBLK) g_boff[t] = sh[t] - v;   // exclusive
}

__global__ void scan_c_kernel() {
    __shared__ int sh[256];
    int t = threadIdx.x, b = blockIdx.x;
    int node = b * 256 + t;
    int v = (node < N_NODES) ? g_deg[node] : 0;
    sh[t] = v;
    __syncthreads();
    #pragma unroll
    for (int d = 1; d < 256; d <<= 1) {
        int x = (t >= d) ? sh[t - d] : 0;
        __syncthreads();
        sh[t] += x;
        __syncthreads();
    }
    if (node < N_NODES) {
        int off = g_boff[b] + sh[t] - v;
        g_off[node] = off;
        g_cursor[node] = off;
    }
}

// ---------------- pass B: permute records into CSR order --------------------
__global__ void fill_kernel() {
    int e = blockIdx.x * blockDim.x + threadIdx.x;
    if (e >= N_EDGES) return;
    int4 p = g_packed[e];
    int pos = atomicAdd(&g_cursor[p.x], 1);
    g_csr[pos] = p;
}

// ------- pass C: gather-side weighted aggregation (fp16 tables, no atomics) -
__device__ __forceinline__ void gather_edge(int a, int v, float s, int lane,
                                            float4& accA, float4& accV) {
    uint2 ua = *reinterpret_cast<const uint2*>(g_attH + a * KD + lane * 4);
    __half2 h0 = *reinterpret_cast<__half2*>(&ua.x);
    __half2 h1 = *reinterpret_cast<__half2*>(&ua.y);
    float2 f0 = __half22float2(h0);
    float2 f1 = __half22float2(h1);
    accA.x += f0.x * s; accA.y += f0.y * s;
    accA.z += f1.x * s; accA.w += f1.y * s;
    if (lane < 16) {
        uint2 uv = *reinterpret_cast<const uint2*>(g_valH + v * VD + lane * 4);
        __half2 g0 = *reinterpret_cast<__half2*>(&uv.x);
        __half2 g1 = *reinterpret_cast<__half2*>(&uv.y);
        float2 e0 = __half22float2(g0);
        float2 e1 = __half22float2(g1);
        accV.x += e0.x * s; accV.y += e0.y * s;
        accV.z += e1.x * s; accV.w += e1.y * s;
    }
}

__global__ void aggregate_kernel() {
    int warp = (blockIdx.x * blockDim.x + threadIdx.x) >> 5;
    int lane = threadIdx.x & 31;
    if (warp >= N_NODES) return;
    int beg = g_off[warp];
    int deg = g_deg[warp];

    float4 accA = make_float4(0.f, 0.f, 0.f, 0.f);
    float4 accV = make_float4(0.f, 0.f, 0.f, 0.f);

    for (int base = 0; base < deg; base += 32) {
        int4 r = make_int4(0, 0, 0, 0);
        if (base + lane < deg) r = g_csr[beg + base + lane];
        int m = min(32, deg - base);
        int i = 0;
        for (; i + 4 <= m; i += 4) {
            int   A[4], V[4];
            float S[4];
            #pragma unroll
            for (int u = 0; u < 4; u++) {
                A[u] = __shfl_sync(0xFFFFFFFFu, r.y, i + u);
                V[u] = __shfl_sync(0xFFFFFFFFu, r.z, i + u);
                S[u] = __int_as_float(__shfl_sync(0xFFFFFFFFu, r.w, i + u));
            }
            #pragma unroll
            for (int u = 0; u < 4; u++)
                gather_edge(A[u], V[u], S[u], lane, accA, accV);
        }
        for (; i < m; i++) {
            int   a = __shfl_sync(0xFFFFFFFFu, r.y, i);
            int   v = __shfl_sync(0xFFFFFFFFu, r.z, i);
            float s = __int_as_float(__shfl_sync(0xFFFFFFFFu, r.w, i));
            gather_edge(a, v, s, lane, accA, accV);
        }
    }

    float* dst = g_agg + warp * AGGD;
    *reinterpret_cast<float4*>(dst + lane * 4) = accA;
    if (lane < 16)
        *reinterpret_cast<float4*>(dst + KD + lane * 4) = accV;
}

// ---------------- node GEMM (192x128) + normalization + ELU -----------------
#define NODES_PER_WARP 8
#define NODE_WARPS 8
#define NODE_THREADS (NODE_WARPS * 32)
#define NODES_PER_BLOCK (NODES_PER_WARP * NODE_WARPS)  // 64

__device__ __forceinline__ unsigned long long pack2(float x, float y) {
    unsigned long long r;
    asm("mov.b64 %0, {%1, %2};" : "=l"(r) : "f"(x), "f"(y));
    return r;
}
__device__ __forceinline__ void unpack2(unsigned long long p, float& x, float& y) {
    asm("mov.b64 {%0, %1}, %2;" : "=f"(x), "=f"(y) : "l"(p));
}
__device__ __forceinline__ void ffma2(unsigned long long& d,
                                      unsigned long long a,
                                      unsigned long long b) {
    asm("fma.rn.f32x2 %0, %1, %2, %0;" : "+l"(d) : "l"(a), "l"(b));
}

__global__ void __launch_bounds__(NODE_THREADS, 2)
node_kernel(const float* __restrict__ ent,
            const float* __restrict__ W,
            float* __restrict__ out) {
    extern __shared__ float Wsh[];   // [192][128] = 98304 B

    int tid  = threadIdx.x;
    int wid  = tid >> 5;
    int lane = tid & 31;

    for (int i = tid; i < AGGD * KD / 4; i += NODE_THREADS)
        reinterpret_cast<float4*>(Wsh)[i] = reinterpret_cast<const float4*>(W)[i];
    __syncthreads();

    const float4* agg4 = reinterpret_cast<const float4*>(g_agg);
    int n_tiles = (N_NODES + NODES_PER_BLOCK - 1) / NODES_PER_BLOCK;

    for (int tile = blockIdx.x; tile < n_tiles; tile += gridDim.x) {
        int nbase = tile * NODES_PER_BLOCK + wid * NODES_PER_WARP;

        unsigned long long acc01[NODES_PER_WARP], acc23[NODES_PER_WARP];
        #pragma unroll
        for (int n = 0; n < NODES_PER_WARP; n++) { acc01[n] = 0ull; acc23[n] = 0ull; }

        #pragma unroll 1
        for (int j = 0; j < AGGD; j += 4) {
            float4 aj[NODES_PER_WARP];
            #pragma unroll
            for (int n = 0; n < NODES_PER_WARP; n++) {
                int node = nbase + n;
                aj[n] = (node < N_NODES)
                    ? __ldg(&agg4[node * (AGGD / 4) + (j >> 2)])
                    : make_float4(0.f, 0.f, 0.f, 0.f);
            }
            #pragma unroll
            for (int jj = 0; jj < 4; jj++) {
                float4 w = reinterpret_cast<const float4*>(Wsh)[(j + jj) * 32 + lane];
                unsigned long long w01 = pack2(w.x, w.y);
                unsigned long long w23 = pack2(w.z, w.w);
                #pragma unroll
                for (int n = 0; n < NODES_PER_WARP; n++) {
                    float a = (jj == 0) ? aj[n].x : (jj == 1) ? aj[n].y
                             : (jj == 2) ? aj[n].z : aj[n].w;
                    unsigned long long aa = pack2(a, a);
                    ffma2(acc01[n], aa, w01);
                    ffma2(acc23[n], aa, w23);
                }
            }
        }

        #pragma unroll
        for (int n = 0; n < NODES_PER_WARP; n++) {
            int node = nbase + n;
            if (node >= N_NODES) break;
            float c0, c1, c2, c3;
            unpack2(acc01[n], c0, c1);
            unpack2(acc23[n], c2, c3);

            float rs = g_rowsum[node];
            float inv = rs > 0.f ? 1.f / rs : 0.f;
            float4 e = reinterpret_cast<const float4*>(ent)[node * 32 + lane];

            float t0 = c0 * inv + e.x;
            float t1 = c1 * inv + e.y;
            float t2 = c2 * inv + e.z;
            float t3 = c3 * inv + e.w;
            float4 o;
            o.x = t0 > 0.f ? t0 : expm1f(t0);   // elu, alpha=1
            o.y = t1 > 0.f ? t1 : expm1f(t1);
            o.z = t2 > 0.f ? t2 : expm1f(t2);
            o.w = t3 > 0.f ? t3 : expm1f(t3);
            reinterpret_cast<float4*>(out)[node * 32 + lane] = o;
        }
    }
}

// ---------------- launch ----------------------------------------------------
extern "C" void kernel_launch(void* const* d_in, const int* in_sizes, int n_in,
                              void* d_out, int out_size) {
    const void*  triples = d_in[0];                       // [1e6, 3] int64/int32
    const float* ent     = (const float*)d_in[1];         // [1e5, 128]
    const float* attf    = (const float*)d_in[2];         // [1e5, 128]
    const float* valf    = (const float*)d_in[3];         // [1e5, 64]
    const float* aw      = (const float*)d_in[4];         // [256]
    const float* ab      = (const float*)d_in[5];         // [1]
    const float* W       = (const float*)d_in[6];         // [192, 128]
    float* out           = (float*)d_out;                 // [1e5, 128]

    static bool attr_set = false;
    size_t node_smem = (size_t)(AGGD * KD) * sizeof(float);   // 98304
    if (!attr_set) {
        cudaFuncSetAttribute(node_kernel, cudaFuncAttributeMaxDynamicSharedMemorySize,
                             (int)node_smem);
        attr_set = true;
    }

    sniff_kernel<<<1, 256>>>((const int*)triples);
    score_pre_kernel<<<(N_NODES + 7) / 8, 256>>>(ent, attf, aw);
    valconv_kernel<<<(N_NODES * VD / 4 + 255) / 256, 256>>>(valf);
    score_edge_kernel<<<(N_EDGES + 255) / 256, 256>>>(triples, ab);
    scan_a_kernel<<<NBLK, 256>>>();
    scan_b_kernel<<<1, 512>>>();
    scan_c_kernel<<<NBLK, 256>>>();
    fill_kernel<<<(N_EDGES + 255) / 256, 256>>>();
    aggregate_kernel<<<(N_NODES * 32 + 255) / 256, 256>>>();
    node_kernel<<<296, NODE_THREADS, node_smem>>>(ent, W, out);
}